// round 11
// baseline (speedup 1.0000x reference)
#include <cuda_runtime.h>
#include <cuda_fp16.h>
#include <cstdint>

// Problem constants
#define B_    8192
#define C_    4096
#define G_    8
#define HID_  1024
#define CTRL_ 64
#define NH_   (G_*HID_)

// GEMM tiling (fp16 elements)
#define BM 128
#define BN 128
#define BK 64                        // halves per K-chunk
#define ROWA 144                     // A row: 128B data + 16B pad
#define ROWBB 272                    // B row: 256B data + 16B pad
#define A_BYTES (BM*ROWA)            // 18432
#define B_BYTES (BK*ROWBB)           // 17408
#define STAGE_BYTES (A_BYTES + B_BYTES)   // 35840
#define STAGES 2
#define SMEM_BYTES (STAGES*STAGE_BYTES)   // 71680  (x3 CTAs = 215040)
#define GM 16                        // m-tiles per rasterization group
#define NT 128                       // threads per CTA (4 warps)

// Scratch (static device arrays: sanctioned workaround for alloc guard)
__device__ __half g_xh [(size_t)B_ * C_];
__device__ __half g_w1h[(size_t)C_ * HID_ * G_];  // natural [G][C][HID]
__device__ __half g_w2h[(size_t)NH_ * C_];        // natural [NH][C]
__device__ __half g_H  [(size_t)B_ * NH_];
__device__ float  g_choose[B_ * G_];

// ---------------------------------------------------------------------------
// helpers
// ---------------------------------------------------------------------------
__device__ __forceinline__ unsigned h2_bits(__half2 h) {
    return *reinterpret_cast<unsigned*>(&h);
}

__device__ __forceinline__ uint32_t smem_u32(const void* p) {
    uint32_t a;
    asm("{ .reg .u64 t; cvta.to.shared.u64 t, %1; cvt.u32.u64 %0, t; }" : "=r"(a) : "l"(p));
    return a;
}

__device__ __forceinline__ void cp_async16(uint32_t dst, const void* src) {
    asm volatile("cp.async.cg.shared.global [%0], [%1], 16;" :: "r"(dst), "l"(src) : "memory");
}

__device__ __forceinline__ void ldsm4(uint32_t r[4], uint32_t saddr) {
    asm volatile("ldmatrix.sync.aligned.m8n8.x4.shared.b16 {%0,%1,%2,%3}, [%4];"
        : "=r"(r[0]), "=r"(r[1]), "=r"(r[2]), "=r"(r[3]) : "r"(saddr));
}

__device__ __forceinline__ void ldsm4t(uint32_t r[4], uint32_t saddr) {
    asm volatile("ldmatrix.sync.aligned.m8n8.x4.trans.shared.b16 {%0,%1,%2,%3}, [%4];"
        : "=r"(r[0]), "=r"(r[1]), "=r"(r[2]), "=r"(r[3]) : "r"(saddr));
}

__device__ __forceinline__ void mma_f16(float c[4], const uint32_t a[4],
                                        uint32_t b0, uint32_t b1) {
    asm volatile(
        "mma.sync.aligned.m16n8k16.row.col.f32.f16.f16.f32 "
        "{%0,%1,%2,%3}, {%4,%5,%6,%7}, {%8,%9}, {%0,%1,%2,%3};"
        : "+f"(c[0]), "+f"(c[1]), "+f"(c[2]), "+f"(c[3])
        : "r"(a[0]), "r"(a[1]), "r"(a[2]), "r"(a[3]), "r"(b0), "r"(b1));
}

// rasterization: GM m-tiles per group, m fastest within group
__device__ __forceinline__ void tile_map(int Ntiles, int& mt, int& nt) {
    const int bid = blockIdx.x;
    const int per_g = GM * Ntiles;
    const int grp = bid / per_g;
    const int rem = bid - grp * per_g;
    mt = grp * GM + (rem % GM);
    nt = rem / GM;
}

// ---------------------------------------------------------------------------
// mainloop (compile-time K and LDB): acc[4][8][4] = A[m0:+128,:K] @ B[:K, tile]
// A row-major [M,K]; B natural row-major [K,N] (row stride LDB), Bg offset to
// the tile's first column. 4 warps, warp tile 64x64, 2-stage smem pipeline.
// All cp.async / ldsm addresses are base + compile-time constant.
// ---------------------------------------------------------------------------
template<int K, int LDB>
__device__ __forceinline__ void mainloop_t(const __half* __restrict__ A, int m0,
                                           const __half* __restrict__ Bg,
                                           char* smem, float (&acc)[4][8][4])
{
    const int tid  = threadIdx.x;
    const int lane = tid & 31;
    const int warp = tid >> 5;
    const int wm = (warp & 1) * 64;   // 2 warps in M
    const int wn = (warp >> 1) * 64;  // 2 warps in N
    const uint32_t sbase = smem_u32(smem);

#pragma unroll
    for (int i = 0; i < 4; i++)
#pragma unroll
        for (int j = 0; j < 8; j++)
#pragma unroll
            for (int k = 0; k < 4; k++) acc[i][j][k] = 0.f;

    // per-thread global bases (computed once; advanced by constants per iter)
    const __half* aPtr = A + ((size_t)m0 + (tid >> 3)) * K + (tid & 7) * 8;
    const __half* bPtr = Bg + (size_t)(tid >> 4) * LDB + (tid & 15) * 8;
    // per-thread smem store offsets (constant)
    const uint32_t sAoff = (uint32_t)((tid >> 3) * ROWA + (tid & 7) * 16);
    const uint32_t sBoff = (uint32_t)(A_BYTES + (tid >> 4) * ROWBB + (tid & 15) * 16);

    const int T = K / BK;

    // prologue: stage 0
#pragma unroll
    for (int i = 0; i < 8; i++)
        cp_async16(sbase + sAoff + i * (16 * ROWA), aPtr + (size_t)(16 * i) * K);
#pragma unroll
    for (int i = 0; i < 8; i++)
        cp_async16(sbase + sBoff + i * (8 * ROWBB), bPtr + (size_t)(8 * i) * LDB);
    asm volatile("cp.async.commit_group;" ::: "memory");
    aPtr += BK;
    bPtr += (size_t)BK * LDB;

    // ldsm read offsets (constant per thread)
    const uint32_t aOff = (uint32_t)((wm + (lane & 15)) * ROWA + (lane >> 4) * 16);
    const int brow = (lane & 7) + ((lane >> 4) & 1) * 8;
    const uint32_t bOff = (uint32_t)(A_BYTES + brow * ROWBB
                                     + (wn + ((lane >> 3) & 1) * 8) * 2);

    for (int t = 0; t < T; t++) {
        asm volatile("cp.async.wait_group 0;" ::: "memory");
        __syncthreads();

        if (t + 1 < T) {
            const uint32_t s2 = sbase + (uint32_t)(((t + 1) & 1) * STAGE_BYTES);
#pragma unroll
            for (int i = 0; i < 8; i++)
                cp_async16(s2 + sAoff + i * (16 * ROWA), aPtr + (size_t)(16 * i) * K);
#pragma unroll
            for (int i = 0; i < 8; i++)
                cp_async16(s2 + sBoff + i * (8 * ROWBB), bPtr + (size_t)(8 * i) * LDB);
            asm volatile("cp.async.commit_group;" ::: "memory");
            aPtr += BK;
            bPtr += (size_t)BK * LDB;
        }

        const uint32_t st = sbase + (uint32_t)((t & 1) * STAGE_BYTES);
#pragma unroll
        for (int k16 = 0; k16 < 4; k16++) {
            uint32_t a[4][4], bf[4][4];
#pragma unroll
            for (int im = 0; im < 4; im++)
                ldsm4(a[im], st + aOff + im * (16 * ROWA) + k16 * 32);
#pragma unroll
            for (int j = 0; j < 4; j++)
                ldsm4t(bf[j], st + bOff + k16 * (16 * ROWBB) + j * 32);
#pragma unroll
            for (int im = 0; im < 4; im++)
#pragma unroll
                for (int j = 0; j < 4; j++) {
                    mma_f16(acc[im][2 * j],     a[im], bf[j][0], bf[j][2]);
                    mma_f16(acc[im][2 * j + 1], a[im], bf[j][1], bf[j][3]);
                }
        }
    }
    __syncthreads();   // smem safe for epilogue reuse
}

// ---------------------------------------------------------------------------
// GEMM1: H[m, n] = fp16( relu(x @ w1[g,:,h] + b1[g,h]) * choose[m, g] )
// ---------------------------------------------------------------------------
__global__ void __launch_bounds__(NT, 3)
gemm1_k(const __half* __restrict__ A, const __half* __restrict__ Bw,
        const float* __restrict__ b1)
{
    extern __shared__ char smem[];
    int mt, nt;
    tile_map(NH_ / BN, mt, nt);
    const int m0 = mt * BM, n0 = nt * BN;
    const int g = n0 / HID_;
    const int h0 = n0 % HID_;

    float acc[4][8][4];
    mainloop_t<C_, HID_>(A, m0, Bw + (size_t)g * C_ * HID_ + h0, smem, acc);

    const int tid = threadIdx.x, lane = tid & 31, warp = tid >> 5;
    const int wm = (warp & 1) * 64, wn = (warp >> 1) * 64;
    const int g8 = lane >> 2, tg = lane & 3;
    const float* b1g = b1 + (size_t)g * HID_ + h0;

#pragma unroll
    for (int im = 0; im < 4; im++) {
        const int r0 = m0 + wm + 16 * im + g8;
        const float ch0 = g_choose[r0 * G_ + g];
        const float ch1 = g_choose[(r0 + 8) * G_ + g];
#pragma unroll
        for (int in = 0; in < 8; in++) {
            const int cl = wn + 8 * in + 2 * tg;
            const float bb0 = __ldg(b1g + cl);
            const float bb1 = __ldg(b1g + cl + 1);
            __half2 v0 = __floats2half2_rn(fmaxf(acc[im][in][0] + bb0, 0.f) * ch0,
                                           fmaxf(acc[im][in][1] + bb1, 0.f) * ch0);
            __half2 v1 = __floats2half2_rn(fmaxf(acc[im][in][2] + bb0, 0.f) * ch1,
                                           fmaxf(acc[im][in][3] + bb1, 0.f) * ch1);
            *reinterpret_cast<__half2*>(&g_H[(size_t)r0 * NH_ + n0 + cl]) = v0;
            *reinterpret_cast<__half2*>(&g_H[(size_t)(r0 + 8) * NH_ + n0 + cl]) = v1;
        }
    }
}

// ---------------------------------------------------------------------------
// GEMM2: out[m, c] = H @ w2[:, c] + sum_g choose[m,g] * b2[g,c]
// ---------------------------------------------------------------------------
__global__ void __launch_bounds__(NT, 3)
gemm2_k(const __half* __restrict__ A, const __half* __restrict__ Bw,
        const float* __restrict__ b2, float* __restrict__ out)
{
    extern __shared__ char smem[];
    int mt, nt;
    tile_map(C_ / BN, mt, nt);
    const int m0 = mt * BM, n0 = nt * BN;

    float acc[4][8][4];
    mainloop_t<NH_, C_>(A, m0, Bw + n0, smem, acc);

    // stage b2 tile [G][BN] in smem
    float* sB2 = (float*)smem;
    const int tid = threadIdx.x;
    for (int i = tid; i < G_ * BN; i += NT)
        sB2[i] = b2[(size_t)(i >> 7) * C_ + n0 + (i & 127)];
    __syncthreads();

    const int lane = tid & 31, warp = tid >> 5;
    const int wm = (warp & 1) * 64, wn = (warp >> 1) * 64;
    const int g8 = lane >> 2, tg = lane & 3;

#pragma unroll
    for (int im = 0; im < 4; im++) {
        const int r0 = m0 + wm + 16 * im + g8;
        float c0[G_], c1[G_];
        *reinterpret_cast<float4*>(&c0[0]) = *reinterpret_cast<const float4*>(&g_choose[r0 * G_]);
        *reinterpret_cast<float4*>(&c0[4]) = *reinterpret_cast<const float4*>(&g_choose[r0 * G_ + 4]);
        *reinterpret_cast<float4*>(&c1[0]) = *reinterpret_cast<const float4*>(&g_choose[(r0 + 8) * G_]);
        *reinterpret_cast<float4*>(&c1[4]) = *reinterpret_cast<const float4*>(&g_choose[(r0 + 8) * G_ + 4]);
#pragma unroll
        for (int in = 0; in < 8; in++) {
            const int cl = wn + 8 * in + 2 * tg;
            float b00 = 0.f, b01 = 0.f, b10 = 0.f, b11 = 0.f;
#pragma unroll
            for (int gg = 0; gg < G_; gg++) {
                const float w0  = sB2[gg * BN + cl];
                const float w1v = sB2[gg * BN + cl + 1];
                b00 += c0[gg] * w0;  b01 += c0[gg] * w1v;
                b10 += c1[gg] * w0;  b11 += c1[gg] * w1v;
            }
            float2 v0, v1;
            v0.x = acc[im][in][0] + b00;  v0.y = acc[im][in][1] + b01;
            v1.x = acc[im][in][2] + b10;  v1.y = acc[im][in][3] + b11;
            *reinterpret_cast<float2*>(&out[(size_t)r0 * C_ + n0 + cl]) = v0;
            *reinterpret_cast<float2*>(&out[(size_t)(r0 + 8) * C_ + n0 + cl]) = v1;
        }
    }
}

// ---------------------------------------------------------------------------
// Pre-pass: fused fp32 -> fp16 conversion of x, w1, w2 (all 33.55M elements)
// ---------------------------------------------------------------------------
#define N8_PER ((size_t)B_ * C_ / 8)   // 4,194,304 uint4-chunks per array

__global__ void __launch_bounds__(256)
f2h_all(const float4* __restrict__ in0, uint4* __restrict__ out0,
        const float4* __restrict__ in1, uint4* __restrict__ out1,
        const float4* __restrict__ in2, uint4* __restrict__ out2)
{
    const size_t total = 3 * N8_PER;
    for (size_t i = (size_t)blockIdx.x * blockDim.x + threadIdx.x; i < total;
         i += (size_t)gridDim.x * blockDim.x) {
        const float4* in;
        uint4* out;
        size_t j;
        if (i < N8_PER)               { in = in0; out = out0; j = i; }
        else if (i < 2 * N8_PER)      { in = in1; out = out1; j = i - N8_PER; }
        else                          { in = in2; out = out2; j = i - 2 * N8_PER; }
        float4 v0 = in[2 * j];
        float4 v1 = in[2 * j + 1];
        uint4 o;
        o.x = h2_bits(__floats2half2_rn(v0.x, v0.y));
        o.y = h2_bits(__floats2half2_rn(v0.z, v0.w));
        o.z = h2_bits(__floats2half2_rn(v1.x, v1.y));
        o.w = h2_bits(__floats2half2_rn(v1.z, v1.w));
        out[j] = o;
    }
}

// ---------------------------------------------------------------------------
// Gate control: choose = softmax(relu(y@wc1+bc1)@wc2+bc2)
// ---------------------------------------------------------------------------
__global__ __launch_bounds__(256)
void gate_kernel(const float* __restrict__ y,
                 const float* __restrict__ wc1, const float* __restrict__ bc1,
                 const float* __restrict__ wc2, const float* __restrict__ bc2)
{
    __shared__ float swc1[CTRL_ * G_];
    __shared__ float swc2[G_ * G_];
    __shared__ float sbc1[G_];
    __shared__ float sbc2[G_];
    const int tid = threadIdx.x;
    for (int i = tid; i < CTRL_ * G_; i += 256) swc1[i] = wc1[i];
    if (tid < G_ * G_) swc2[tid] = wc2[tid];
    if (tid < G_) { sbc1[tid] = bc1[tid]; sbc2[tid] = bc2[tid]; }
    __syncthreads();

    const int b = blockIdx.x * 256 + tid;
    const float* yr = y + (size_t)b * CTRL_;

    float hid[G_];
#pragma unroll
    for (int j = 0; j < G_; j++) hid[j] = sbc1[j];
    for (int c = 0; c < CTRL_; c++) {
        const float yv = yr[c];
#pragma unroll
        for (int j = 0; j < G_; j++) hid[j] += yv * swc1[c * G_ + j];
    }
#pragma unroll
    for (int j = 0; j < G_; j++) hid[j] = fmaxf(hid[j], 0.f);

    float o[G_];
#pragma unroll
    for (int g = 0; g < G_; g++) o[g] = sbc2[g];
#pragma unroll
    for (int j = 0; j < G_; j++)
#pragma unroll
        for (int g = 0; g < G_; g++) o[g] += hid[j] * swc2[j * G_ + g];

    float mx = o[0];
#pragma unroll
    for (int g = 1; g < G_; g++) mx = fmaxf(mx, o[g]);
    float s = 0.f;
#pragma unroll
    for (int g = 0; g < G_; g++) { o[g] = __expf(o[g] - mx); s += o[g]; }
    const float inv = 1.f / s;
#pragma unroll
    for (int g = 0; g < G_; g++) g_choose[b * G_ + g] = o[g] * inv;
}

// ---------------------------------------------------------------------------
extern "C" void kernel_launch(void* const* d_in, const int* in_sizes, int n_in,
                              void* d_out, int out_size)
{
    const float* x   = (const float*)d_in[0];
    const float* y   = (const float*)d_in[1];
    const float* w1  = (const float*)d_in[2];
    const float* b1  = (const float*)d_in[3];
    const float* w2  = (const float*)d_in[4];
    const float* b2  = (const float*)d_in[5];
    const float* wc1 = (const float*)d_in[6];
    const float* bc1 = (const float*)d_in[7];
    const float* wc2 = (const float*)d_in[8];
    const float* bc2 = (const float*)d_in[9];
    float* out = (float*)d_out;

    cudaFuncSetAttribute(gemm1_k, cudaFuncAttributeMaxDynamicSharedMemorySize, SMEM_BYTES);
    cudaFuncSetAttribute(gemm2_k, cudaFuncAttributeMaxDynamicSharedMemorySize, SMEM_BYTES);

    __half* dxh;  cudaGetSymbolAddress((void**)&dxh,  g_xh);
    __half* dw1h; cudaGetSymbolAddress((void**)&dw1h, g_w1h);
    __half* dw2h; cudaGetSymbolAddress((void**)&dw2h, g_w2h);
    __half* dH;   cudaGetSymbolAddress((void**)&dH,   g_H);

    f2h_all<<<2048, 256>>>((const float4*)x,  (uint4*)dxh,
                           (const float4*)w1, (uint4*)dw1h,
                           (const float4*)w2, (uint4*)dw2h);
    gate_kernel<<<B_ / 256, 256>>>(y, wc1, bc1, wc2, bc2);
    gemm1_k<<<(B_ / BM) * (NH_ / BN), NT, SMEM_BYTES>>>(dxh, dw1h, b1);
    gemm2_k<<<(B_ / BM) * (C_ / BN), NT, SMEM_BYTES>>>(dH, dw2h, b2, out);
}

// round 12
// speedup vs baseline: 1.0943x; 1.0943x over previous
#include <cuda_runtime.h>
#include <cuda_fp16.h>
#include <cstdint>

// Problem constants
#define B_    8192
#define C_    4096
#define G_    8
#define HID_  1024
#define CTRL_ 64
#define NH_   (G_*HID_)

// GEMM tiling (fp16 elements)
#define BM 128
#define BN 128
#define BK 64                        // halves per K-chunk
#define ROWA 144                     // A row: 128B data + 16B pad
#define ROWBB 272                    // B row: 256B data + 16B pad
#define A_BYTES (BM*ROWA)            // 18432
#define B_BYTES (BK*ROWBB)           // 17408
#define STAGE_BYTES (A_BYTES + B_BYTES)   // 35840
#define STAGES 2
#define SMEM_BYTES (STAGES*STAGE_BYTES)   // 71680  (x3 CTAs = 215040)
#define GM 16                        // m-tiles per rasterization group
#define NT 128                       // threads per CTA (4 warps)

// Scratch (static device arrays: sanctioned workaround for alloc guard)
__device__ __half g_xh [(size_t)B_ * C_];
__device__ __half g_w1h[(size_t)C_ * HID_ * G_];  // natural [G][C][HID]
__device__ __half g_w2h[(size_t)NH_ * C_];        // natural [NH][C]
__device__ __half g_H  [(size_t)B_ * NH_];
__device__ float  g_choose[B_ * G_];

// ---------------------------------------------------------------------------
// helpers
// ---------------------------------------------------------------------------
__device__ __forceinline__ unsigned h2_bits(__half2 h) {
    return *reinterpret_cast<unsigned*>(&h);
}

__device__ __forceinline__ uint32_t smem_u32(const void* p) {
    uint32_t a;
    asm("{ .reg .u64 t; cvta.to.shared.u64 t, %1; cvt.u32.u64 %0, t; }" : "=r"(a) : "l"(p));
    return a;
}

__device__ __forceinline__ void cp_async16(uint32_t dst, const void* src) {
    asm volatile("cp.async.cg.shared.global [%0], [%1], 16;" :: "r"(dst), "l"(src) : "memory");
}

__device__ __forceinline__ void ldsm4(uint32_t r[4], uint32_t saddr) {
    asm volatile("ldmatrix.sync.aligned.m8n8.x4.shared.b16 {%0,%1,%2,%3}, [%4];"
        : "=r"(r[0]), "=r"(r[1]), "=r"(r[2]), "=r"(r[3]) : "r"(saddr));
}

__device__ __forceinline__ void ldsm4t(uint32_t r[4], uint32_t saddr) {
    asm volatile("ldmatrix.sync.aligned.m8n8.x4.trans.shared.b16 {%0,%1,%2,%3}, [%4];"
        : "=r"(r[0]), "=r"(r[1]), "=r"(r[2]), "=r"(r[3]) : "r"(saddr));
}

__device__ __forceinline__ void mma_f16(float c[4], const uint32_t a[4],
                                        uint32_t b0, uint32_t b1) {
    asm volatile(
        "mma.sync.aligned.m16n8k16.row.col.f32.f16.f16.f32 "
        "{%0,%1,%2,%3}, {%4,%5,%6,%7}, {%8,%9}, {%0,%1,%2,%3};"
        : "+f"(c[0]), "+f"(c[1]), "+f"(c[2]), "+f"(c[3])
        : "r"(a[0]), "r"(a[1]), "r"(a[2]), "r"(a[3]), "r"(b0), "r"(b1));
}

// rasterization: GM m-tiles per group, m fastest within group
__device__ __forceinline__ void tile_map(int Ntiles, int& mt, int& nt) {
    const int bid = blockIdx.x;
    const int per_g = GM * Ntiles;
    const int grp = bid / per_g;
    const int rem = bid - grp * per_g;
    mt = grp * GM + (rem % GM);
    nt = rem / GM;
}

// ---------------------------------------------------------------------------
// cp.async tile issue: A [BM x BK] from [M,K] (lda=K), B [BK x BN] from [K,N]
// (R10 form — dynamic K/ldb; ptxas schedules this best)
// ---------------------------------------------------------------------------
__device__ __forceinline__ void issue_tile(uint32_t sA, uint32_t sB,
                                           const __half* Ag, const __half* Bg,
                                           int K, int ldb, int tid)
{
#pragma unroll
    for (int i = 0; i < 8; i++) {                 // A: 128 rows x 8 chunks
        const int id = tid + NT * i;
        const int row = id >> 3, c = id & 7;
        cp_async16(sA + row * ROWA + c * 16, Ag + (size_t)row * K + c * 8);
    }
#pragma unroll
    for (int i = 0; i < 8; i++) {                 // B: 64 rows x 16 chunks
        const int id = tid + NT * i;
        const int row = id >> 4, c = id & 15;
        cp_async16(sB + row * ROWBB + c * 16, Bg + (size_t)row * ldb + c * 8);
    }
}

// one k-iteration body: wait, prefetch next stage, compute current stage
__device__ __forceinline__ void iter_body(
    uint32_t stCur, uint32_t stNext, bool prefetch,
    const __half* Ag, const __half* Bg, int K, int ldb, int tNext, int tid,
    uint32_t aOff, uint32_t bOff, float (&acc)[4][8][4])
{
    asm volatile("cp.async.wait_group 0;" ::: "memory");
    __syncthreads();

    if (prefetch) {
        issue_tile(stNext, stNext + A_BYTES,
                   Ag + (size_t)tNext * BK,
                   Bg + (size_t)tNext * BK * ldb, K, ldb, tid);
        asm volatile("cp.async.commit_group;" ::: "memory");
    }

#pragma unroll
    for (int k16 = 0; k16 < 4; k16++) {
        uint32_t a[4][4], bf[4][4];
#pragma unroll
        for (int im = 0; im < 4; im++)
            ldsm4(a[im], stCur + aOff + im * (16 * ROWA) + k16 * 32);
#pragma unroll
        for (int j = 0; j < 4; j++)
            ldsm4t(bf[j], stCur + bOff + k16 * (16 * ROWBB) + j * 32);
#pragma unroll
        for (int im = 0; im < 4; im++)
#pragma unroll
            for (int j = 0; j < 4; j++) {
                mma_f16(acc[im][2 * j],     a[im], bf[j][0], bf[j][2]);
                mma_f16(acc[im][2 * j + 1], a[im], bf[j][1], bf[j][3]);
            }
    }
}

// ---------------------------------------------------------------------------
// mainloop: acc[4][8][4] = A[m0:m0+128, :K] @ B[:K, n-block]
// A row-major [M,K]; B natural row-major [K,N] with row stride ldb.
// 4 warps, warp tile 64x64, 2-stage smem pipeline (3 CTAs/SM).
// t-loop unrolled x2 so both stage bases are compile-time offsets.
// ---------------------------------------------------------------------------
__device__ __forceinline__ void mainloop(const __half* __restrict__ A,
                                         int K, int m0,
                                         const __half* __restrict__ Bg, int ldb,
                                         char* smem, float (&acc)[4][8][4])
{
    const int tid  = threadIdx.x;
    const int lane = tid & 31;
    const int warp = tid >> 5;
    const int wm = (warp & 1) * 64;   // 2 warps in M
    const int wn = (warp >> 1) * 64;  // 2 warps in N
    const uint32_t sbase = smem_u32(smem);

#pragma unroll
    for (int i = 0; i < 4; i++)
#pragma unroll
        for (int j = 0; j < 8; j++)
#pragma unroll
            for (int k = 0; k < 4; k++) acc[i][j][k] = 0.f;

    const __half* Ag = A + (size_t)m0 * K;
    const int T = K / BK;             // always even (64 or 128)

    // prologue: stage 0
    issue_tile(sbase, sbase + A_BYTES, Ag, Bg, K, ldb, tid);
    asm volatile("cp.async.commit_group;" ::: "memory");

    // ldsm read offsets (constant per thread)
    const uint32_t aOff = (uint32_t)((wm + (lane & 15)) * ROWA + (lane >> 4) * 16);
    const int brow = (lane & 7) + ((lane >> 4) & 1) * 8;
    const uint32_t bOff = (uint32_t)(A_BYTES + brow * ROWBB
                                     + (wn + ((lane >> 3) & 1) * 8) * 2);

    const uint32_t st0 = sbase;
    const uint32_t st1 = sbase + STAGE_BYTES;

    for (int t = 0; t < T; t += 2) {
        // even iter: compute stage0, prefetch into stage1
        iter_body(st0, st1, true, Ag, Bg, K, ldb, t + 1, tid, aOff, bOff, acc);
        // odd iter: compute stage1, prefetch into stage0 (unless last pair)
        iter_body(st1, st0, (t + 2 < T), Ag, Bg, K, ldb, t + 2, tid, aOff, bOff, acc);
    }
    __syncthreads();   // smem safe for epilogue reuse
}

// ---------------------------------------------------------------------------
// GEMM1: H[m, n] = fp16( relu(x @ w1[g,:,h] + b1[g,h]) * choose[m, g] )
// ---------------------------------------------------------------------------
__global__ void __launch_bounds__(NT, 3)
gemm1_k(const __half* __restrict__ A, const __half* __restrict__ Bw,
        const float* __restrict__ b1)
{
    extern __shared__ char smem[];
    int mt, nt;
    tile_map(NH_ / BN, mt, nt);
    const int m0 = mt * BM, n0 = nt * BN;
    const int g = n0 / HID_;
    const int h0 = n0 % HID_;

    float acc[4][8][4];
    mainloop(A, C_, m0, Bw + (size_t)g * C_ * HID_ + h0, HID_, smem, acc);

    const int tid = threadIdx.x, lane = tid & 31, warp = tid >> 5;
    const int wm = (warp & 1) * 64, wn = (warp >> 1) * 64;
    const int g8 = lane >> 2, tg = lane & 3;
    const float* b1g = b1 + (size_t)g * HID_ + h0;

#pragma unroll
    for (int im = 0; im < 4; im++) {
        const int r0 = m0 + wm + 16 * im + g8;
        const float ch0 = g_choose[r0 * G_ + g];
        const float ch1 = g_choose[(r0 + 8) * G_ + g];
#pragma unroll
        for (int in = 0; in < 8; in++) {
            const int cl = wn + 8 * in + 2 * tg;
            const float bb0 = __ldg(b1g + cl);
            const float bb1 = __ldg(b1g + cl + 1);
            __half2 v0 = __floats2half2_rn(fmaxf(acc[im][in][0] + bb0, 0.f) * ch0,
                                           fmaxf(acc[im][in][1] + bb1, 0.f) * ch0);
            __half2 v1 = __floats2half2_rn(fmaxf(acc[im][in][2] + bb0, 0.f) * ch1,
                                           fmaxf(acc[im][in][3] + bb1, 0.f) * ch1);
            *reinterpret_cast<__half2*>(&g_H[(size_t)r0 * NH_ + n0 + cl]) = v0;
            *reinterpret_cast<__half2*>(&g_H[(size_t)(r0 + 8) * NH_ + n0 + cl]) = v1;
        }
    }
}

// ---------------------------------------------------------------------------
// GEMM2: out[m, c] = H @ w2[:, c] + sum_g choose[m,g] * b2[g,c]
// ---------------------------------------------------------------------------
__global__ void __launch_bounds__(NT, 3)
gemm2_k(const __half* __restrict__ A, const __half* __restrict__ Bw,
        const float* __restrict__ b2, float* __restrict__ out)
{
    extern __shared__ char smem[];
    int mt, nt;
    tile_map(C_ / BN, mt, nt);
    const int m0 = mt * BM, n0 = nt * BN;

    float acc[4][8][4];
    mainloop(A, NH_, m0, Bw + n0, C_, smem, acc);

    // stage b2 tile [G][BN] in smem
    float* sB2 = (float*)smem;
    const int tid = threadIdx.x;
    for (int i = tid; i < G_ * BN; i += NT)
        sB2[i] = b2[(size_t)(i >> 7) * C_ + n0 + (i & 127)];
    __syncthreads();

    const int lane = tid & 31, warp = tid >> 5;
    const int wm = (warp & 1) * 64, wn = (warp >> 1) * 64;
    const int g8 = lane >> 2, tg = lane & 3;

#pragma unroll
    for (int im = 0; im < 4; im++) {
        const int r0 = m0 + wm + 16 * im + g8;
        float c0[G_], c1[G_];
        *reinterpret_cast<float4*>(&c0[0]) = *reinterpret_cast<const float4*>(&g_choose[r0 * G_]);
        *reinterpret_cast<float4*>(&c0[4]) = *reinterpret_cast<const float4*>(&g_choose[r0 * G_ + 4]);
        *reinterpret_cast<float4*>(&c1[0]) = *reinterpret_cast<const float4*>(&g_choose[(r0 + 8) * G_]);
        *reinterpret_cast<float4*>(&c1[4]) = *reinterpret_cast<const float4*>(&g_choose[(r0 + 8) * G_ + 4]);
#pragma unroll
        for (int in = 0; in < 8; in++) {
            const int cl = wn + 8 * in + 2 * tg;
            float b00 = 0.f, b01 = 0.f, b10 = 0.f, b11 = 0.f;
#pragma unroll
            for (int gg = 0; gg < G_; gg++) {
                const float w0  = sB2[gg * BN + cl];
                const float w1v = sB2[gg * BN + cl + 1];
                b00 += c0[gg] * w0;  b01 += c0[gg] * w1v;
                b10 += c1[gg] * w0;  b11 += c1[gg] * w1v;
            }
            float2 v0, v1;
            v0.x = acc[im][in][0] + b00;  v0.y = acc[im][in][1] + b01;
            v1.x = acc[im][in][2] + b10;  v1.y = acc[im][in][3] + b11;
            *reinterpret_cast<float2*>(&out[(size_t)r0 * C_ + n0 + cl]) = v0;
            *reinterpret_cast<float2*>(&out[(size_t)(r0 + 8) * C_ + n0 + cl]) = v1;
        }
    }
}

// ---------------------------------------------------------------------------
// Pre-pass: fused fp32->fp16 conversion of x, w1, w2 PLUS the control gate.
// Blocks [0, 2048) convert; blocks [2048, 2080) run the gate MLP+softmax.
// ---------------------------------------------------------------------------
#define N8_PER ((size_t)B_ * C_ / 8)   // 4,194,304 uint4-chunks per array
#define CONV_BLOCKS 2048
#define GATE_BLOCKS (B_ / 256)         // 32

__global__ void __launch_bounds__(256)
prep_all(const float4* __restrict__ in0, uint4* __restrict__ out0,
         const float4* __restrict__ in1, uint4* __restrict__ out1,
         const float4* __restrict__ in2, uint4* __restrict__ out2,
         const float* __restrict__ y,
         const float* __restrict__ wc1, const float* __restrict__ bc1,
         const float* __restrict__ wc2, const float* __restrict__ bc2)
{
    const int tid = threadIdx.x;

    if (blockIdx.x >= CONV_BLOCKS) {
        // ----- gate control: choose = softmax(relu(y@wc1+bc1)@wc2+bc2) -----
        __shared__ float swc1[CTRL_ * G_];
        __shared__ float swc2[G_ * G_];
        __shared__ float sbc1[G_];
        __shared__ float sbc2[G_];
        for (int i = tid; i < CTRL_ * G_; i += 256) swc1[i] = wc1[i];
        if (tid < G_ * G_) swc2[tid] = wc2[tid];
        if (tid < G_) { sbc1[tid] = bc1[tid]; sbc2[tid] = bc2[tid]; }
        __syncthreads();

        const int b = (blockIdx.x - CONV_BLOCKS) * 256 + tid;
        const float* yr = y + (size_t)b * CTRL_;

        float hid[G_];
#pragma unroll
        for (int j = 0; j < G_; j++) hid[j] = sbc1[j];
        for (int c = 0; c < CTRL_; c++) {
            const float yv = yr[c];
#pragma unroll
            for (int j = 0; j < G_; j++) hid[j] += yv * swc1[c * G_ + j];
        }
#pragma unroll
        for (int j = 0; j < G_; j++) hid[j] = fmaxf(hid[j], 0.f);

        float o[G_];
#pragma unroll
        for (int g = 0; g < G_; g++) o[g] = sbc2[g];
#pragma unroll
        for (int j = 0; j < G_; j++)
#pragma unroll
            for (int g = 0; g < G_; g++) o[g] += hid[j] * swc2[j * G_ + g];

        float mx = o[0];
#pragma unroll
        for (int g = 1; g < G_; g++) mx = fmaxf(mx, o[g]);
        float s = 0.f;
#pragma unroll
        for (int g = 0; g < G_; g++) { o[g] = __expf(o[g] - mx); s += o[g]; }
        const float inv = 1.f / s;
#pragma unroll
        for (int g = 0; g < G_; g++) g_choose[b * G_ + g] = o[g] * inv;
        return;
    }

    // ----- fp32 -> fp16 conversions -----
    const size_t total = 3 * N8_PER;
    for (size_t i = (size_t)blockIdx.x * 256 + tid; i < total;
         i += (size_t)CONV_BLOCKS * 256) {
        const float4* in;
        uint4* out;
        size_t j;
        if (i < N8_PER)               { in = in0; out = out0; j = i; }
        else if (i < 2 * N8_PER)      { in = in1; out = out1; j = i - N8_PER; }
        else                          { in = in2; out = out2; j = i - 2 * N8_PER; }
        float4 v0 = in[2 * j];
        float4 v1 = in[2 * j + 1];
        uint4 o;
        o.x = h2_bits(__floats2half2_rn(v0.x, v0.y));
        o.y = h2_bits(__floats2half2_rn(v0.z, v0.w));
        o.z = h2_bits(__floats2half2_rn(v1.x, v1.y));
        o.w = h2_bits(__floats2half2_rn(v1.z, v1.w));
        out[j] = o;
    }
}

// ---------------------------------------------------------------------------
extern "C" void kernel_launch(void* const* d_in, const int* in_sizes, int n_in,
                              void* d_out, int out_size)
{
    const float* x   = (const float*)d_in[0];
    const float* y   = (const float*)d_in[1];
    const float* w1  = (const float*)d_in[2];
    const float* b1  = (const float*)d_in[3];
    const float* w2  = (const float*)d_in[4];
    const float* b2  = (const float*)d_in[5];
    const float* wc1 = (const float*)d_in[6];
    const float* bc1 = (const float*)d_in[7];
    const float* wc2 = (const float*)d_in[8];
    const float* bc2 = (const float*)d_in[9];
    float* out = (float*)d_out;

    cudaFuncSetAttribute(gemm1_k, cudaFuncAttributeMaxDynamicSharedMemorySize, SMEM_BYTES);
    cudaFuncSetAttribute(gemm2_k, cudaFuncAttributeMaxDynamicSharedMemorySize, SMEM_BYTES);

    __half* dxh;  cudaGetSymbolAddress((void**)&dxh,  g_xh);
    __half* dw1h; cudaGetSymbolAddress((void**)&dw1h, g_w1h);
    __half* dw2h; cudaGetSymbolAddress((void**)&dw2h, g_w2h);
    __half* dH;   cudaGetSymbolAddress((void**)&dH,   g_H);

    prep_all<<<CONV_BLOCKS + GATE_BLOCKS, 256>>>(
        (const float4*)x,  (uint4*)dxh,
        (const float4*)w1, (uint4*)dw1h,
        (const float4*)w2, (uint4*)dw2h,
        y, wc1, bc1, wc2, bc2);
    gemm1_k<<<(B_ / BM) * (NH_ / BN), NT, SMEM_BYTES>>>(dxh, dw1h, b1);
    gemm2_k<<<(B_ / BM) * (C_ / BN), NT, SMEM_BYTES>>>(dH, dw2h, b2, out);
}

// round 13
// speedup vs baseline: 1.1655x; 1.0651x over previous
#include <cuda_runtime.h>
#include <cuda_fp16.h>
#include <cstdint>

// Problem constants
#define B_    8192
#define C_    4096
#define G_    8
#define HID_  1024
#define CTRL_ 64
#define NH_   (G_*HID_)

// GEMM tiling (fp16 elements)
#define BM 128
#define BN 128
#define BK 64                        // halves per K-chunk
#define ROWA 144                     // A row: 128B data + 16B pad
#define ROWBB 272                    // B row: 256B data + 16B pad
#define A_BYTES (BM*ROWA)            // 18432
#define B_BYTES (BK*ROWBB)           // 17408
#define STAGE_BYTES (A_BYTES + B_BYTES)   // 35840
#define STAGES 2
#define SMEM_BYTES (STAGES*STAGE_BYTES)   // 71680  (x3 CTAs = 215040)
#define GM 16                        // m-tiles per rasterization group
#define NT 128                       // threads per CTA (4 warps)

// Scratch (static device arrays: sanctioned workaround for alloc guard)
__device__ __half g_xh [(size_t)B_ * C_];
__device__ __half g_w1h[(size_t)C_ * HID_ * G_];  // natural [G][C][HID]
__device__ __half g_w2h[(size_t)NH_ * C_];        // natural [NH][C]
__device__ __half g_H  [(size_t)B_ * NH_];
__device__ float  g_choose[B_ * G_];

// ---------------------------------------------------------------------------
// helpers
// ---------------------------------------------------------------------------
__device__ __forceinline__ unsigned h2_bits(__half2 h) {
    return *reinterpret_cast<unsigned*>(&h);
}

__device__ __forceinline__ uint32_t smem_u32(const void* p) {
    uint32_t a;
    asm("{ .reg .u64 t; cvta.to.shared.u64 t, %1; cvt.u32.u64 %0, t; }" : "=r"(a) : "l"(p));
    return a;
}

__device__ __forceinline__ void cp_async16(uint32_t dst, const void* src) {
    asm volatile("cp.async.cg.shared.global [%0], [%1], 16;" :: "r"(dst), "l"(src) : "memory");
}

__device__ __forceinline__ void ldsm4(uint32_t r[4], uint32_t saddr) {
    asm volatile("ldmatrix.sync.aligned.m8n8.x4.shared.b16 {%0,%1,%2,%3}, [%4];"
        : "=r"(r[0]), "=r"(r[1]), "=r"(r[2]), "=r"(r[3]) : "r"(saddr));
}

__device__ __forceinline__ void ldsm4t(uint32_t r[4], uint32_t saddr) {
    asm volatile("ldmatrix.sync.aligned.m8n8.x4.trans.shared.b16 {%0,%1,%2,%3}, [%4];"
        : "=r"(r[0]), "=r"(r[1]), "=r"(r[2]), "=r"(r[3]) : "r"(saddr));
}

__device__ __forceinline__ void mma_f16(float c[4], const uint32_t a[4],
                                        uint32_t b0, uint32_t b1) {
    asm volatile(
        "mma.sync.aligned.m16n8k16.row.col.f32.f16.f16.f32 "
        "{%0,%1,%2,%3}, {%4,%5,%6,%7}, {%8,%9}, {%0,%1,%2,%3};"
        : "+f"(c[0]), "+f"(c[1]), "+f"(c[2]), "+f"(c[3])
        : "r"(a[0]), "r"(a[1]), "r"(a[2]), "r"(a[3]), "r"(b0), "r"(b1));
}

// rasterization: GM m-tiles per group, m fastest within group
__device__ __forceinline__ void tile_map(int Ntiles, int& mt, int& nt) {
    const int bid = blockIdx.x;
    const int per_g = GM * Ntiles;
    const int grp = bid / per_g;
    const int rem = bid - grp * per_g;
    mt = grp * GM + (rem % GM);
    nt = rem / GM;
}

// ---------------------------------------------------------------------------
// cp.async tile issue: A [BM x BK] from [M,K] (lda=K), B [BK x BN] from [K,N]
// (R10 form — dynamic K/ldb; ptxas schedules this best)
// ---------------------------------------------------------------------------
__device__ __forceinline__ void issue_tile(uint32_t sA, uint32_t sB,
                                           const __half* Ag, const __half* Bg,
                                           int K, int ldb, int tid)
{
#pragma unroll
    for (int i = 0; i < 8; i++) {                 // A: 128 rows x 8 chunks
        const int id = tid + NT * i;
        const int row = id >> 3, c = id & 7;
        cp_async16(sA + row * ROWA + c * 16, Ag + (size_t)row * K + c * 8);
    }
#pragma unroll
    for (int i = 0; i < 8; i++) {                 // B: 64 rows x 16 chunks
        const int id = tid + NT * i;
        const int row = id >> 4, c = id & 15;
        cp_async16(sB + row * ROWBB + c * 16, Bg + (size_t)row * ldb + c * 8);
    }
}

// ---------------------------------------------------------------------------
// mainloop (exact R10 form): acc[4][8][4] = A[m0:+128, :K] @ B[:K, n-block]
// A row-major [M,K]; B natural row-major [K,N] with row stride ldb.
// 4 warps, warp tile 64x64, 2-stage smem pipeline (3 CTAs/SM).
// ---------------------------------------------------------------------------
__device__ __forceinline__ void mainloop(const __half* __restrict__ A,
                                         int K, int m0,
                                         const __half* __restrict__ Bg, int ldb,
                                         char* smem, float (&acc)[4][8][4])
{
    const int tid  = threadIdx.x;
    const int lane = tid & 31;
    const int warp = tid >> 5;
    const int wm = (warp & 1) * 64;   // 2 warps in M
    const int wn = (warp >> 1) * 64;  // 2 warps in N
    const uint32_t sbase = smem_u32(smem);

#pragma unroll
    for (int i = 0; i < 4; i++)
#pragma unroll
        for (int j = 0; j < 8; j++)
#pragma unroll
            for (int k = 0; k < 4; k++) acc[i][j][k] = 0.f;

    const __half* Ag = A + (size_t)m0 * K;
    const int T = K / BK;

    // prologue: stage 0
    issue_tile(sbase, sbase + A_BYTES, Ag, Bg, K, ldb, tid);
    asm volatile("cp.async.commit_group;" ::: "memory");

    // ldsm read offsets (constant per thread)
    const uint32_t aOff = (uint32_t)((wm + (lane & 15)) * ROWA + (lane >> 4) * 16);
    const int brow = (lane & 7) + ((lane >> 4) & 1) * 8;
    const uint32_t bOff = (uint32_t)(A_BYTES + brow * ROWBB
                                     + (wn + ((lane >> 3) & 1) * 8) * 2);

    for (int t = 0; t < T; t++) {
        asm volatile("cp.async.wait_group 0;" ::: "memory");
        __syncthreads();

        if (t + 1 < T) {
            const int s2 = (t + 1) & 1;
            issue_tile(sbase + s2 * STAGE_BYTES,
                       sbase + s2 * STAGE_BYTES + A_BYTES,
                       Ag + (size_t)(t + 1) * BK,
                       Bg + (size_t)(t + 1) * BK * ldb, K, ldb, tid);
            asm volatile("cp.async.commit_group;" ::: "memory");
        }

        const uint32_t st = sbase + (uint32_t)((t & 1) * STAGE_BYTES);
#pragma unroll
        for (int k16 = 0; k16 < 4; k16++) {
            uint32_t a[4][4], bf[4][4];
#pragma unroll
            for (int im = 0; im < 4; im++)
                ldsm4(a[im], st + aOff + im * (16 * ROWA) + k16 * 32);
#pragma unroll
            for (int j = 0; j < 4; j++)
                ldsm4t(bf[j], st + bOff + k16 * (16 * ROWBB) + j * 32);
#pragma unroll
            for (int im = 0; im < 4; im++)
#pragma unroll
                for (int j = 0; j < 4; j++) {
                    mma_f16(acc[im][2 * j],     a[im], bf[j][0], bf[j][2]);
                    mma_f16(acc[im][2 * j + 1], a[im], bf[j][1], bf[j][3]);
                }
        }
    }
    __syncthreads();   // smem safe for epilogue reuse
}

// ---------------------------------------------------------------------------
// GEMM1: H[m, n] = fp16( relu(x @ w1[g,:,h] + b1[g,h]) * choose[m, g] )
// ---------------------------------------------------------------------------
__global__ void __launch_bounds__(NT, 3)
gemm1_k(const __half* __restrict__ A, const __half* __restrict__ Bw,
        const float* __restrict__ b1)
{
    extern __shared__ char smem[];
    int mt, nt;
    tile_map(NH_ / BN, mt, nt);
    const int m0 = mt * BM, n0 = nt * BN;
    const int g = n0 / HID_;
    const int h0 = n0 % HID_;

    float acc[4][8][4];
    mainloop(A, C_, m0, Bw + (size_t)g * C_ * HID_ + h0, HID_, smem, acc);

    const int tid = threadIdx.x, lane = tid & 31, warp = tid >> 5;
    const int wm = (warp & 1) * 64, wn = (warp >> 1) * 64;
    const int g8 = lane >> 2, tg = lane & 3;
    const float* b1g = b1 + (size_t)g * HID_ + h0;

#pragma unroll
    for (int im = 0; im < 4; im++) {
        const int r0 = m0 + wm + 16 * im + g8;
        const float ch0 = g_choose[r0 * G_ + g];
        const float ch1 = g_choose[(r0 + 8) * G_ + g];
#pragma unroll
        for (int in = 0; in < 8; in++) {
            const int cl = wn + 8 * in + 2 * tg;
            const float bb0 = __ldg(b1g + cl);
            const float bb1 = __ldg(b1g + cl + 1);
            __half2 v0 = __floats2half2_rn(fmaxf(acc[im][in][0] + bb0, 0.f) * ch0,
                                           fmaxf(acc[im][in][1] + bb1, 0.f) * ch0);
            __half2 v1 = __floats2half2_rn(fmaxf(acc[im][in][2] + bb0, 0.f) * ch1,
                                           fmaxf(acc[im][in][3] + bb1, 0.f) * ch1);
            *reinterpret_cast<__half2*>(&g_H[(size_t)r0 * NH_ + n0 + cl]) = v0;
            *reinterpret_cast<__half2*>(&g_H[(size_t)(r0 + 8) * NH_ + n0 + cl]) = v1;
        }
    }
}

// ---------------------------------------------------------------------------
// GEMM2: out[m, c] = H @ w2[:, c] + sum_g choose[m,g] * b2[g,c]
// ---------------------------------------------------------------------------
__global__ void __launch_bounds__(NT, 3)
gemm2_k(const __half* __restrict__ A, const __half* __restrict__ Bw,
        const float* __restrict__ b2, float* __restrict__ out)
{
    extern __shared__ char smem[];
    int mt, nt;
    tile_map(C_ / BN, mt, nt);
    const int m0 = mt * BM, n0 = nt * BN;

    float acc[4][8][4];
    mainloop(A, NH_, m0, Bw + n0, C_, smem, acc);

    // stage b2 tile [G][BN] in smem
    float* sB2 = (float*)smem;
    const int tid = threadIdx.x;
    for (int i = tid; i < G_ * BN; i += NT)
        sB2[i] = b2[(size_t)(i >> 7) * C_ + n0 + (i & 127)];
    __syncthreads();

    const int lane = tid & 31, warp = tid >> 5;
    const int wm = (warp & 1) * 64, wn = (warp >> 1) * 64;
    const int g8 = lane >> 2, tg = lane & 3;

#pragma unroll
    for (int im = 0; im < 4; im++) {
        const int r0 = m0 + wm + 16 * im + g8;
        float c0[G_], c1[G_];
        *reinterpret_cast<float4*>(&c0[0]) = *reinterpret_cast<const float4*>(&g_choose[r0 * G_]);
        *reinterpret_cast<float4*>(&c0[4]) = *reinterpret_cast<const float4*>(&g_choose[r0 * G_ + 4]);
        *reinterpret_cast<float4*>(&c1[0]) = *reinterpret_cast<const float4*>(&g_choose[(r0 + 8) * G_]);
        *reinterpret_cast<float4*>(&c1[4]) = *reinterpret_cast<const float4*>(&g_choose[(r0 + 8) * G_ + 4]);
#pragma unroll
        for (int in = 0; in < 8; in++) {
            const int cl = wn + 8 * in + 2 * tg;
            float b00 = 0.f, b01 = 0.f, b10 = 0.f, b11 = 0.f;
#pragma unroll
            for (int gg = 0; gg < G_; gg++) {
                const float w0  = sB2[gg * BN + cl];
                const float w1v = sB2[gg * BN + cl + 1];
                b00 += c0[gg] * w0;  b01 += c0[gg] * w1v;
                b10 += c1[gg] * w0;  b11 += c1[gg] * w1v;
            }
            float2 v0, v1;
            v0.x = acc[im][in][0] + b00;  v0.y = acc[im][in][1] + b01;
            v1.x = acc[im][in][2] + b10;  v1.y = acc[im][in][3] + b11;
            *reinterpret_cast<float2*>(&out[(size_t)r0 * C_ + n0 + cl]) = v0;
            *reinterpret_cast<float2*>(&out[(size_t)(r0 + 8) * C_ + n0 + cl]) = v1;
        }
    }
}

// ---------------------------------------------------------------------------
// Pre-pass: fused fp32->fp16 conversion of x, w1, w2 PLUS the control gate.
// Blocks [0, 2048) convert; blocks [2048, 2080) run the gate MLP+softmax.
// ---------------------------------------------------------------------------
#define N8_PER ((size_t)B_ * C_ / 8)   // 4,194,304 uint4-chunks per array
#define CONV_BLOCKS 2048
#define GATE_BLOCKS (B_ / 256)         // 32

__global__ void __launch_bounds__(256)
prep_all(const float4* __restrict__ in0, uint4* __restrict__ out0,
         const float4* __restrict__ in1, uint4* __restrict__ out1,
         const float4* __restrict__ in2, uint4* __restrict__ out2,
         const float* __restrict__ y,
         const float* __restrict__ wc1, const float* __restrict__ bc1,
         const float* __restrict__ wc2, const float* __restrict__ bc2)
{
    const int tid = threadIdx.x;

    if (blockIdx.x >= CONV_BLOCKS) {
        // ----- gate control: choose = softmax(relu(y@wc1+bc1)@wc2+bc2) -----
        __shared__ float swc1[CTRL_ * G_];
        __shared__ float swc2[G_ * G_];
        __shared__ float sbc1[G_];
        __shared__ float sbc2[G_];
        for (int i = tid; i < CTRL_ * G_; i += 256) swc1[i] = wc1[i];
        if (tid < G_ * G_) swc2[tid] = wc2[tid];
        if (tid < G_) { sbc1[tid] = bc1[tid]; sbc2[tid] = bc2[tid]; }
        __syncthreads();

        const int b = (blockIdx.x - CONV_BLOCKS) * 256 + tid;
        const float* yr = y + (size_t)b * CTRL_;

        float hid[G_];
#pragma unroll
        for (int j = 0; j < G_; j++) hid[j] = sbc1[j];
        for (int c = 0; c < CTRL_; c++) {
            const float yv = yr[c];
#pragma unroll
            for (int j = 0; j < G_; j++) hid[j] += yv * swc1[c * G_ + j];
        }
#pragma unroll
        for (int j = 0; j < G_; j++) hid[j] = fmaxf(hid[j], 0.f);

        float o[G_];
#pragma unroll
        for (int g = 0; g < G_; g++) o[g] = sbc2[g];
#pragma unroll
        for (int j = 0; j < G_; j++)
#pragma unroll
            for (int g = 0; g < G_; g++) o[g] += hid[j] * swc2[j * G_ + g];

        float mx = o[0];
#pragma unroll
        for (int g = 1; g < G_; g++) mx = fmaxf(mx, o[g]);
        float s = 0.f;
#pragma unroll
        for (int g = 0; g < G_; g++) { o[g] = __expf(o[g] - mx); s += o[g]; }
        const float inv = 1.f / s;
#pragma unroll
        for (int g = 0; g < G_; g++) g_choose[b * G_ + g] = o[g] * inv;
        return;
    }

    // ----- fp32 -> fp16 conversions -----
    const size_t total = 3 * N8_PER;
    for (size_t i = (size_t)blockIdx.x * 256 + tid; i < total;
         i += (size_t)CONV_BLOCKS * 256) {
        const float4* in;
        uint4* out;
        size_t j;
        if (i < N8_PER)               { in = in0; out = out0; j = i; }
        else if (i < 2 * N8_PER)      { in = in1; out = out1; j = i - N8_PER; }
        else                          { in = in2; out = out2; j = i - 2 * N8_PER; }
        float4 v0 = in[2 * j];
        float4 v1 = in[2 * j + 1];
        uint4 o;
        o.x = h2_bits(__floats2half2_rn(v0.x, v0.y));
        o.y = h2_bits(__floats2half2_rn(v0.z, v0.w));
        o.z = h2_bits(__floats2half2_rn(v1.x, v1.y));
        o.w = h2_bits(__floats2half2_rn(v1.z, v1.w));
        out[j] = o;
    }
}

// ---------------------------------------------------------------------------
extern "C" void kernel_launch(void* const* d_in, const int* in_sizes, int n_in,
                              void* d_out, int out_size)
{
    const float* x   = (const float*)d_in[0];
    const float* y   = (const float*)d_in[1];
    const float* w1  = (const float*)d_in[2];
    const float* b1  = (const float*)d_in[3];
    const float* w2  = (const float*)d_in[4];
    const float* b2  = (const float*)d_in[5];
    const float* wc1 = (const float*)d_in[6];
    const float* bc1 = (const float*)d_in[7];
    const float* wc2 = (const float*)d_in[8];
    const float* bc2 = (const float*)d_in[9];
    float* out = (float*)d_out;

    cudaFuncSetAttribute(gemm1_k, cudaFuncAttributeMaxDynamicSharedMemorySize, SMEM_BYTES);
    cudaFuncSetAttribute(gemm2_k, cudaFuncAttributeMaxDynamicSharedMemorySize, SMEM_BYTES);

    __half* dxh;  cudaGetSymbolAddress((void**)&dxh,  g_xh);
    __half* dw1h; cudaGetSymbolAddress((void**)&dw1h, g_w1h);
    __half* dw2h; cudaGetSymbolAddress((void**)&dw2h, g_w2h);
    __half* dH;   cudaGetSymbolAddress((void**)&dH,   g_H);

    prep_all<<<CONV_BLOCKS + GATE_BLOCKS, 256>>>(
        (const float4*)x,  (uint4*)dxh,
        (const float4*)w1, (uint4*)dw1h,
        (const float4*)w2, (uint4*)dw2h,
        y, wc1, bc1, wc2, bc2);
    gemm1_k<<<(B_ / BM) * (NH_ / BN), NT, SMEM_BYTES>>>(dxh, dw1h, b1);
    gemm2_k<<<(B_ / BM) * (C_ / BN), NT, SMEM_BYTES>>>(dH, dw2h, b2, out);
}

// round 14
// speedup vs baseline: 1.1706x; 1.0044x over previous
#include <cuda_runtime.h>
#include <cuda_fp16.h>
#include <cstdint>

// Problem constants
#define B_    8192
#define C_    4096
#define G_    8
#define HID_  1024
#define CTRL_ 64
#define NH_   (G_*HID_)

// GEMM tiling (fp16 elements)
#define BM 128
#define BN 128
#define BK 64                        // halves per K-chunk
#define ROWA 144                     // A row: 128B data + 16B pad
#define ROWBB 272                    // B row: 256B data + 16B pad
#define A_BYTES (BM*ROWA)            // 18432
#define B_BYTES (BK*ROWBB)           // 17408
#define STAGE_BYTES (A_BYTES + B_BYTES)   // 35840
#define STAGES 2
#define SMEM_BYTES (STAGES*STAGE_BYTES)   // 71680  (x3 CTAs = 215040)
#define GM 16                        // m-tiles per rasterization group
#define NT 128                       // threads per CTA (4 warps)

// Scratch (static device arrays: sanctioned workaround for alloc guard)
__device__ __half g_xh [(size_t)B_ * C_];
__device__ __half g_w1h[(size_t)C_ * HID_ * G_];  // natural [G][C][HID]
__device__ __half g_w2h[(size_t)NH_ * C_];        // natural [NH][C]
__device__ __half g_H  [(size_t)B_ * NH_];
__device__ float  g_choose[B_ * G_];

// ---------------------------------------------------------------------------
// helpers
// ---------------------------------------------------------------------------
__device__ __forceinline__ unsigned h2_bits(__half2 h) {
    return *reinterpret_cast<unsigned*>(&h);
}

__device__ __forceinline__ uint32_t smem_u32(const void* p) {
    uint32_t a;
    asm("{ .reg .u64 t; cvta.to.shared.u64 t, %1; cvt.u32.u64 %0, t; }" : "=r"(a) : "l"(p));
    return a;
}

__device__ __forceinline__ void cp_async16(uint32_t dst, const void* src) {
    asm volatile("cp.async.cg.shared.global [%0], [%1], 16;" :: "r"(dst), "l"(src) : "memory");
}

__device__ __forceinline__ void ldsm4(uint32_t r[4], uint32_t saddr) {
    asm volatile("ldmatrix.sync.aligned.m8n8.x4.shared.b16 {%0,%1,%2,%3}, [%4];"
        : "=r"(r[0]), "=r"(r[1]), "=r"(r[2]), "=r"(r[3]) : "r"(saddr));
}

__device__ __forceinline__ void ldsm4t(uint32_t r[4], uint32_t saddr) {
    asm volatile("ldmatrix.sync.aligned.m8n8.x4.trans.shared.b16 {%0,%1,%2,%3}, [%4];"
        : "=r"(r[0]), "=r"(r[1]), "=r"(r[2]), "=r"(r[3]) : "r"(saddr));
}

__device__ __forceinline__ void mma_f16(float c[4], const uint32_t a[4],
                                        uint32_t b0, uint32_t b1) {
    asm volatile(
        "mma.sync.aligned.m16n8k16.row.col.f32.f16.f16.f32 "
        "{%0,%1,%2,%3}, {%4,%5,%6,%7}, {%8,%9}, {%0,%1,%2,%3};"
        : "+f"(c[0]), "+f"(c[1]), "+f"(c[2]), "+f"(c[3])
        : "r"(a[0]), "r"(a[1]), "r"(a[2]), "r"(a[3]), "r"(b0), "r"(b1));
}

// rasterization: GM m-tiles per group, m fastest within group
__device__ __forceinline__ void tile_map(int Ntiles, int& mt, int& nt) {
    const int bid = blockIdx.x;
    const int per_g = GM * Ntiles;
    const int grp = bid / per_g;
    const int rem = bid - grp * per_g;
    mt = grp * GM + (rem % GM);
    nt = rem / GM;
}

// ---------------------------------------------------------------------------
// cp.async tile issue: A [BM x BK] from [M,K] (lda=K), B [BK x BN] from [K,N]
// (R10 form — dynamic K/ldb; ptxas schedules this best)
// ---------------------------------------------------------------------------
__device__ __forceinline__ void issue_tile(uint32_t sA, uint32_t sB,
                                           const __half* Ag, const __half* Bg,
                                           int K, int ldb, int tid)
{
#pragma unroll
    for (int i = 0; i < 8; i++) {                 // A: 128 rows x 8 chunks
        const int id = tid + NT * i;
        const int row = id >> 3, c = id & 7;
        cp_async16(sA + row * ROWA + c * 16, Ag + (size_t)row * K + c * 8);
    }
#pragma unroll
    for (int i = 0; i < 8; i++) {                 // B: 64 rows x 16 chunks
        const int id = tid + NT * i;
        const int row = id >> 4, c = id & 15;
        cp_async16(sB + row * ROWBB + c * 16, Bg + (size_t)row * ldb + c * 8);
    }
}

// ---------------------------------------------------------------------------
// mainloop (exact R10 form): acc[4][8][4] = A[m0:+128, :K] @ B[:K, n-block]
// A row-major [M,K]; B natural row-major [K,N] with row stride ldb.
// 4 warps, warp tile 64x64, 2-stage smem pipeline (3 CTAs/SM).
// ---------------------------------------------------------------------------
__device__ __forceinline__ void mainloop(const __half* __restrict__ A,
                                         int K, int m0,
                                         const __half* __restrict__ Bg, int ldb,
                                         char* smem, float (&acc)[4][8][4])
{
    const int tid  = threadIdx.x;
    const int lane = tid & 31;
    const int warp = tid >> 5;
    const int wm = (warp & 1) * 64;   // 2 warps in M
    const int wn = (warp >> 1) * 64;  // 2 warps in N
    const uint32_t sbase = smem_u32(smem);

#pragma unroll
    for (int i = 0; i < 4; i++)
#pragma unroll
        for (int j = 0; j < 8; j++)
#pragma unroll
            for (int k = 0; k < 4; k++) acc[i][j][k] = 0.f;

    const __half* Ag = A + (size_t)m0 * K;
    const int T = K / BK;

    // prologue: stage 0
    issue_tile(sbase, sbase + A_BYTES, Ag, Bg, K, ldb, tid);
    asm volatile("cp.async.commit_group;" ::: "memory");

    // ldsm read offsets (constant per thread)
    const uint32_t aOff = (uint32_t)((wm + (lane & 15)) * ROWA + (lane >> 4) * 16);
    const int brow = (lane & 7) + ((lane >> 4) & 1) * 8;
    const uint32_t bOff = (uint32_t)(A_BYTES + brow * ROWBB
                                     + (wn + ((lane >> 3) & 1) * 8) * 2);

    for (int t = 0; t < T; t++) {
        asm volatile("cp.async.wait_group 0;" ::: "memory");
        __syncthreads();

        if (t + 1 < T) {
            const int s2 = (t + 1) & 1;
            issue_tile(sbase + s2 * STAGE_BYTES,
                       sbase + s2 * STAGE_BYTES + A_BYTES,
                       Ag + (size_t)(t + 1) * BK,
                       Bg + (size_t)(t + 1) * BK * ldb, K, ldb, tid);
            asm volatile("cp.async.commit_group;" ::: "memory");
        }

        const uint32_t st = sbase + (uint32_t)((t & 1) * STAGE_BYTES);
#pragma unroll
        for (int k16 = 0; k16 < 4; k16++) {
            uint32_t a[4][4], bf[4][4];
#pragma unroll
            for (int im = 0; im < 4; im++)
                ldsm4(a[im], st + aOff + im * (16 * ROWA) + k16 * 32);
#pragma unroll
            for (int j = 0; j < 4; j++)
                ldsm4t(bf[j], st + bOff + k16 * (16 * ROWBB) + j * 32);
#pragma unroll
            for (int im = 0; im < 4; im++)
#pragma unroll
                for (int j = 0; j < 4; j++) {
                    mma_f16(acc[im][2 * j],     a[im], bf[j][0], bf[j][2]);
                    mma_f16(acc[im][2 * j + 1], a[im], bf[j][1], bf[j][3]);
                }
        }
    }
    __syncthreads();   // smem safe for epilogue reuse
}

// ---------------------------------------------------------------------------
// GEMM1: H[m, n] = fp16( relu(x @ w1[g,:,h] + b1[g,h]) * choose[m, g] )
// ---------------------------------------------------------------------------
__global__ void __launch_bounds__(NT, 3)
gemm1_k(const __half* __restrict__ A, const __half* __restrict__ Bw,
        const float* __restrict__ b1)
{
    extern __shared__ char smem[];
    int mt, nt;
    tile_map(NH_ / BN, mt, nt);
    const int m0 = mt * BM, n0 = nt * BN;
    const int g = n0 / HID_;
    const int h0 = n0 % HID_;

    float acc[4][8][4];
    mainloop(A, C_, m0, Bw + (size_t)g * C_ * HID_ + h0, HID_, smem, acc);

    const int tid = threadIdx.x, lane = tid & 31, warp = tid >> 5;
    const int wm = (warp & 1) * 64, wn = (warp >> 1) * 64;
    const int g8 = lane >> 2, tg = lane & 3;
    const float* b1g = b1 + (size_t)g * HID_ + h0;

#pragma unroll
    for (int im = 0; im < 4; im++) {
        const int r0 = m0 + wm + 16 * im + g8;
        const float ch0 = g_choose[r0 * G_ + g];
        const float ch1 = g_choose[(r0 + 8) * G_ + g];
#pragma unroll
        for (int in = 0; in < 8; in++) {
            const int cl = wn + 8 * in + 2 * tg;
            const float bb0 = __ldg(b1g + cl);
            const float bb1 = __ldg(b1g + cl + 1);
            __half2 v0 = __floats2half2_rn(fmaxf(acc[im][in][0] + bb0, 0.f) * ch0,
                                           fmaxf(acc[im][in][1] + bb1, 0.f) * ch0);
            __half2 v1 = __floats2half2_rn(fmaxf(acc[im][in][2] + bb0, 0.f) * ch1,
                                           fmaxf(acc[im][in][3] + bb1, 0.f) * ch1);
            *reinterpret_cast<__half2*>(&g_H[(size_t)r0 * NH_ + n0 + cl]) = v0;
            *reinterpret_cast<__half2*>(&g_H[(size_t)(r0 + 8) * NH_ + n0 + cl]) = v1;
        }
    }
}

// ---------------------------------------------------------------------------
// GEMM2: out[m, c] = H @ w2[:, c] + sum_g choose[m,g] * b2[g,c]
// ---------------------------------------------------------------------------
__global__ void __launch_bounds__(NT, 3)
gemm2_k(const __half* __restrict__ A, const __half* __restrict__ Bw,
        const float* __restrict__ b2, float* __restrict__ out)
{
    extern __shared__ char smem[];
    int mt, nt;
    tile_map(C_ / BN, mt, nt);
    const int m0 = mt * BM, n0 = nt * BN;

    float acc[4][8][4];
    mainloop(A, NH_, m0, Bw + n0, C_, smem, acc);

    // stage b2 tile [G][BN] in smem
    float* sB2 = (float*)smem;
    const int tid = threadIdx.x;
    for (int i = tid; i < G_ * BN; i += NT)
        sB2[i] = b2[(size_t)(i >> 7) * C_ + n0 + (i & 127)];
    __syncthreads();

    const int lane = tid & 31, warp = tid >> 5;
    const int wm = (warp & 1) * 64, wn = (warp >> 1) * 64;
    const int g8 = lane >> 2, tg = lane & 3;

#pragma unroll
    for (int im = 0; im < 4; im++) {
        const int r0 = m0 + wm + 16 * im + g8;
        float c0[G_], c1[G_];
        *reinterpret_cast<float4*>(&c0[0]) = *reinterpret_cast<const float4*>(&g_choose[r0 * G_]);
        *reinterpret_cast<float4*>(&c0[4]) = *reinterpret_cast<const float4*>(&g_choose[r0 * G_ + 4]);
        *reinterpret_cast<float4*>(&c1[0]) = *reinterpret_cast<const float4*>(&g_choose[(r0 + 8) * G_]);
        *reinterpret_cast<float4*>(&c1[4]) = *reinterpret_cast<const float4*>(&g_choose[(r0 + 8) * G_ + 4]);
#pragma unroll
        for (int in = 0; in < 8; in++) {
            const int cl = wn + 8 * in + 2 * tg;
            float b00 = 0.f, b01 = 0.f, b10 = 0.f, b11 = 0.f;
#pragma unroll
            for (int gg = 0; gg < G_; gg++) {
                const float w0  = sB2[gg * BN + cl];
                const float w1v = sB2[gg * BN + cl + 1];
                b00 += c0[gg] * w0;  b01 += c0[gg] * w1v;
                b10 += c1[gg] * w0;  b11 += c1[gg] * w1v;
            }
            float2 v0, v1;
            v0.x = acc[im][in][0] + b00;  v0.y = acc[im][in][1] + b01;
            v1.x = acc[im][in][2] + b10;  v1.y = acc[im][in][3] + b11;
            *reinterpret_cast<float2*>(&out[(size_t)r0 * C_ + n0 + cl]) = v0;
            *reinterpret_cast<float2*>(&out[(size_t)(r0 + 8) * C_ + n0 + cl]) = v1;
        }
    }
}

// ---------------------------------------------------------------------------
// Pre-pass: fused fp32 -> fp16 conversion of x, w1, w2 (all 33.55M elements)
// ---------------------------------------------------------------------------
#define N8_PER ((size_t)B_ * C_ / 8)   // 4,194,304 uint4-chunks per array

__global__ void __launch_bounds__(256)
f2h_all(const float4* __restrict__ in0, uint4* __restrict__ out0,
        const float4* __restrict__ in1, uint4* __restrict__ out1,
        const float4* __restrict__ in2, uint4* __restrict__ out2)
{
    const size_t total = 3 * N8_PER;
    for (size_t i = (size_t)blockIdx.x * blockDim.x + threadIdx.x; i < total;
         i += (size_t)gridDim.x * blockDim.x) {
        const float4* in;
        uint4* out;
        size_t j;
        if (i < N8_PER)               { in = in0; out = out0; j = i; }
        else if (i < 2 * N8_PER)      { in = in1; out = out1; j = i - N8_PER; }
        else                          { in = in2; out = out2; j = i - 2 * N8_PER; }
        float4 v0 = in[2 * j];
        float4 v1 = in[2 * j + 1];
        uint4 o;
        o.x = h2_bits(__floats2half2_rn(v0.x, v0.y));
        o.y = h2_bits(__floats2half2_rn(v0.z, v0.w));
        o.z = h2_bits(__floats2half2_rn(v1.x, v1.y));
        o.w = h2_bits(__floats2half2_rn(v1.z, v1.w));
        out[j] = o;
    }
}

// ---------------------------------------------------------------------------
// Gate control: choose = softmax(relu(y@wc1+bc1)@wc2+bc2)
// ---------------------------------------------------------------------------
__global__ __launch_bounds__(256)
void gate_kernel(const float* __restrict__ y,
                 const float* __restrict__ wc1, const float* __restrict__ bc1,
                 const float* __restrict__ wc2, const float* __restrict__ bc2)
{
    __shared__ float swc1[CTRL_ * G_];
    __shared__ float swc2[G_ * G_];
    __shared__ float sbc1[G_];
    __shared__ float sbc2[G_];
    const int tid = threadIdx.x;
    for (int i = tid; i < CTRL_ * G_; i += 256) swc1[i] = wc1[i];
    if (tid < G_ * G_) swc2[tid] = wc2[tid];
    if (tid < G_) { sbc1[tid] = bc1[tid]; sbc2[tid] = bc2[tid]; }
    __syncthreads();

    const int b = blockIdx.x * 256 + tid;
    const float* yr = y + (size_t)b * CTRL_;

    float hid[G_];
#pragma unroll
    for (int j = 0; j < G_; j++) hid[j] = sbc1[j];
    for (int c = 0; c < CTRL_; c++) {
        const float yv = yr[c];
#pragma unroll
        for (int j = 0; j < G_; j++) hid[j] += yv * swc1[c * G_ + j];
    }
#pragma unroll
    for (int j = 0; j < G_; j++) hid[j] = fmaxf(hid[j], 0.f);

    float o[G_];
#pragma unroll
    for (int g = 0; g < G_; g++) o[g] = sbc2[g];
#pragma unroll
    for (int j = 0; j < G_; j++)
#pragma unroll
        for (int g = 0; g < G_; g++) o[g] += hid[j] * swc2[j * G_ + g];

    float mx = o[0];
#pragma unroll
    for (int g = 1; g < G_; g++) mx = fmaxf(mx, o[g]);
    float s = 0.f;
#pragma unroll
    for (int g = 0; g < G_; g++) { o[g] = __expf(o[g] - mx); s += o[g]; }
    const float inv = 1.f / s;
#pragma unroll
    for (int g = 0; g < G_; g++) g_choose[b * G_ + g] = o[g] * inv;
}

// ---------------------------------------------------------------------------
extern "C" void kernel_launch(void* const* d_in, const int* in_sizes, int n_in,
                              void* d_out, int out_size)
{
    const float* x   = (const float*)d_in[0];
    const float* y   = (const float*)d_in[1];
    const float* w1  = (const float*)d_in[2];
    const float* b1  = (const float*)d_in[3];
    const float* w2  = (const float*)d_in[4];
    const float* b2  = (const float*)d_in[5];
    const float* wc1 = (const float*)d_in[6];
    const float* bc1 = (const float*)d_in[7];
    const float* wc2 = (const float*)d_in[8];
    const float* bc2 = (const float*)d_in[9];
    float* out = (float*)d_out;

    cudaFuncSetAttribute(gemm1_k, cudaFuncAttributeMaxDynamicSharedMemorySize, SMEM_BYTES);
    cudaFuncSetAttribute(gemm2_k, cudaFuncAttributeMaxDynamicSharedMemorySize, SMEM_BYTES);

    __half* dxh;  cudaGetSymbolAddress((void**)&dxh,  g_xh);
    __half* dw1h; cudaGetSymbolAddress((void**)&dw1h, g_w1h);
    __half* dw2h; cudaGetSymbolAddress((void**)&dw2h, g_w2h);
    __half* dH;   cudaGetSymbolAddress((void**)&dH,   g_H);

    f2h_all<<<2048, 256>>>((const float4*)x,  (uint4*)dxh,
                           (const float4*)w1, (uint4*)dw1h,
                           (const float4*)w2, (uint4*)dw2h);
    gate_kernel<<<B_ / 256, 256>>>(y, wc1, bc1, wc2, bc2);
    gemm1_k<<<(B_ / BM) * (NH_ / BN), NT, SMEM_BYTES>>>(dxh, dw1h, b1);
    gemm2_k<<<(B_ / BM) * (C_ / BN), NT, SMEM_BYTES>>>(dH, dw2h, b2, out);
}

// round 15
// speedup vs baseline: 1.1719x; 1.0012x over previous
#include <cuda_runtime.h>
#include <cuda_fp16.h>
#include <cstdint>

// Problem constants
#define B_    8192
#define C_    4096
#define G_    8
#define HID_  1024
#define CTRL_ 64
#define NH_   (G_*HID_)

// GEMM tiling (fp16 elements)
#define BM 128
#define BN 128
#define BK 64                        // halves per K-chunk
#define ROWA 144                     // A row: 128B data + 16B pad
#define ROWBB 272                    // B row: 256B data + 16B pad
#define A_BYTES (BM*ROWA)            // 18432
#define B_BYTES (BK*ROWBB)           // 17408
#define STAGE_BYTES (A_BYTES + B_BYTES)   // 35840
#define STAGES 2
#define SMEM_BYTES (STAGES*STAGE_BYTES)   // 71680  (x3 CTAs = 215040)
#define GM 16                        // m-tiles per rasterization group
#define NT 128                       // threads per CTA (4 warps)

// Scratch (static device arrays: sanctioned workaround for alloc guard)
__device__ __half g_xh [(size_t)B_ * C_];
__device__ __half g_w1h[(size_t)C_ * HID_ * G_];  // natural [G][C][HID]
__device__ __half g_w2h[(size_t)NH_ * C_];        // natural [NH][C]
__device__ __half g_H  [(size_t)B_ * NH_];
__device__ float  g_choose[B_ * G_];

// ---------------------------------------------------------------------------
// helpers
// ---------------------------------------------------------------------------
__device__ __forceinline__ unsigned h2_bits(__half2 h) {
    return *reinterpret_cast<unsigned*>(&h);
}

__device__ __forceinline__ uint32_t smem_u32(const void* p) {
    uint32_t a;
    asm("{ .reg .u64 t; cvta.to.shared.u64 t, %1; cvt.u32.u64 %0, t; }" : "=r"(a) : "l"(p));
    return a;
}

__device__ __forceinline__ void cp_async16(uint32_t dst, const void* src) {
    asm volatile("cp.async.cg.shared.global [%0], [%1], 16;" :: "r"(dst), "l"(src) : "memory");
}

__device__ __forceinline__ void ldsm4(uint32_t r[4], uint32_t saddr) {
    asm volatile("ldmatrix.sync.aligned.m8n8.x4.shared.b16 {%0,%1,%2,%3}, [%4];"
        : "=r"(r[0]), "=r"(r[1]), "=r"(r[2]), "=r"(r[3]) : "r"(saddr));
}

__device__ __forceinline__ void ldsm4t(uint32_t r[4], uint32_t saddr) {
    asm volatile("ldmatrix.sync.aligned.m8n8.x4.trans.shared.b16 {%0,%1,%2,%3}, [%4];"
        : "=r"(r[0]), "=r"(r[1]), "=r"(r[2]), "=r"(r[3]) : "r"(saddr));
}

__device__ __forceinline__ void mma_f16(float c[4], const uint32_t a[4],
                                        uint32_t b0, uint32_t b1) {
    asm volatile(
        "mma.sync.aligned.m16n8k16.row.col.f32.f16.f16.f32 "
        "{%0,%1,%2,%3}, {%4,%5,%6,%7}, {%8,%9}, {%0,%1,%2,%3};"
        : "+f"(c[0]), "+f"(c[1]), "+f"(c[2]), "+f"(c[3])
        : "r"(a[0]), "r"(a[1]), "r"(a[2]), "r"(a[3]), "r"(b0), "r"(b1));
}

// rasterization: GM m-tiles per group, m fastest within group
__device__ __forceinline__ void tile_map(int Ntiles, int& mt, int& nt) {
    const int bid = blockIdx.x;
    const int per_g = GM * Ntiles;
    const int grp = bid / per_g;
    const int rem = bid - grp * per_g;
    mt = grp * GM + (rem % GM);
    nt = rem / GM;
}

// ---------------------------------------------------------------------------
// cp.async tile issue: A [BM x BK] from [M,K] (lda=K), B [BK x BN] from [K,N]
// (R10 form — dynamic K/ldb; ptxas schedules this best)
// ---------------------------------------------------------------------------
__device__ __forceinline__ void issue_tile(uint32_t sA, uint32_t sB,
                                           const __half* Ag, const __half* Bg,
                                           int K, int ldb, int tid)
{
#pragma unroll
    for (int i = 0; i < 8; i++) {                 // A: 128 rows x 8 chunks
        const int id = tid + NT * i;
        const int row = id >> 3, c = id & 7;
        cp_async16(sA + row * ROWA + c * 16, Ag + (size_t)row * K + c * 8);
    }
#pragma unroll
    for (int i = 0; i < 8; i++) {                 // B: 64 rows x 16 chunks
        const int id = tid + NT * i;
        const int row = id >> 4, c = id & 15;
        cp_async16(sB + row * ROWBB + c * 16, Bg + (size_t)row * ldb + c * 8);
    }
}

// ---------------------------------------------------------------------------
// mainloop (exact R10 form): acc[4][8][4] = A[m0:+128, :K] @ B[:K, n-block]
// A row-major [M,K]; B natural row-major [K,N] with row stride ldb.
// 4 warps, warp tile 64x64, 2-stage smem pipeline (3 CTAs/SM).
// ---------------------------------------------------------------------------
__device__ __forceinline__ void mainloop(const __half* __restrict__ A,
                                         int K, int m0,
                                         const __half* __restrict__ Bg, int ldb,
                                         char* smem, float (&acc)[4][8][4])
{
    const int tid  = threadIdx.x;
    const int lane = tid & 31;
    const int warp = tid >> 5;
    const int wm = (warp & 1) * 64;   // 2 warps in M
    const int wn = (warp >> 1) * 64;  // 2 warps in N
    const uint32_t sbase = smem_u32(smem);

#pragma unroll
    for (int i = 0; i < 4; i++)
#pragma unroll
        for (int j = 0; j < 8; j++)
#pragma unroll
            for (int k = 0; k < 4; k++) acc[i][j][k] = 0.f;

    const __half* Ag = A + (size_t)m0 * K;
    const int T = K / BK;

    // prologue: stage 0
    issue_tile(sbase, sbase + A_BYTES, Ag, Bg, K, ldb, tid);
    asm volatile("cp.async.commit_group;" ::: "memory");

    // ldsm read offsets (constant per thread)
    const uint32_t aOff = (uint32_t)((wm + (lane & 15)) * ROWA + (lane >> 4) * 16);
    const int brow = (lane & 7) + ((lane >> 4) & 1) * 8;
    const uint32_t bOff = (uint32_t)(A_BYTES + brow * ROWBB
                                     + (wn + ((lane >> 3) & 1) * 8) * 2);

    for (int t = 0; t < T; t++) {
        asm volatile("cp.async.wait_group 0;" ::: "memory");
        __syncthreads();

        if (t + 1 < T) {
            const int s2 = (t + 1) & 1;
            issue_tile(sbase + s2 * STAGE_BYTES,
                       sbase + s2 * STAGE_BYTES + A_BYTES,
                       Ag + (size_t)(t + 1) * BK,
                       Bg + (size_t)(t + 1) * BK * ldb, K, ldb, tid);
            asm volatile("cp.async.commit_group;" ::: "memory");
        }

        const uint32_t st = sbase + (uint32_t)((t & 1) * STAGE_BYTES);
#pragma unroll
        for (int k16 = 0; k16 < 4; k16++) {
            uint32_t a[4][4], bf[4][4];
#pragma unroll
            for (int im = 0; im < 4; im++)
                ldsm4(a[im], st + aOff + im * (16 * ROWA) + k16 * 32);
#pragma unroll
            for (int j = 0; j < 4; j++)
                ldsm4t(bf[j], st + bOff + k16 * (16 * ROWBB) + j * 32);
#pragma unroll
            for (int im = 0; im < 4; im++)
#pragma unroll
                for (int j = 0; j < 4; j++) {
                    mma_f16(acc[im][2 * j],     a[im], bf[j][0], bf[j][2]);
                    mma_f16(acc[im][2 * j + 1], a[im], bf[j][1], bf[j][3]);
                }
        }
    }
    __syncthreads();   // smem safe for epilogue reuse
}

// ---------------------------------------------------------------------------
// GEMM1: H[m, n] = fp16( relu(x @ w1[g,:,h] + b1[g,h]) * choose[m, g] )
// ---------------------------------------------------------------------------
__global__ void __launch_bounds__(NT, 3)
gemm1_k(const __half* __restrict__ A, const __half* __restrict__ Bw,
        const float* __restrict__ b1)
{
    extern __shared__ char smem[];
    int mt, nt;
    tile_map(NH_ / BN, mt, nt);
    const int m0 = mt * BM, n0 = nt * BN;
    const int g = n0 / HID_;
    const int h0 = n0 % HID_;

    float acc[4][8][4];
    mainloop(A, C_, m0, Bw + (size_t)g * C_ * HID_ + h0, HID_, smem, acc);

    const int tid = threadIdx.x, lane = tid & 31, warp = tid >> 5;
    const int wm = (warp & 1) * 64, wn = (warp >> 1) * 64;
    const int g8 = lane >> 2, tg = lane & 3;
    const float* b1g = b1 + (size_t)g * HID_ + h0;

#pragma unroll
    for (int im = 0; im < 4; im++) {
        const int r0 = m0 + wm + 16 * im + g8;
        const float ch0 = g_choose[r0 * G_ + g];
        const float ch1 = g_choose[(r0 + 8) * G_ + g];
#pragma unroll
        for (int in = 0; in < 8; in++) {
            const int cl = wn + 8 * in + 2 * tg;
            const float bb0 = __ldg(b1g + cl);
            const float bb1 = __ldg(b1g + cl + 1);
            __half2 v0 = __floats2half2_rn(fmaxf(acc[im][in][0] + bb0, 0.f) * ch0,
                                           fmaxf(acc[im][in][1] + bb1, 0.f) * ch0);
            __half2 v1 = __floats2half2_rn(fmaxf(acc[im][in][2] + bb0, 0.f) * ch1,
                                           fmaxf(acc[im][in][3] + bb1, 0.f) * ch1);
            *reinterpret_cast<__half2*>(&g_H[(size_t)r0 * NH_ + n0 + cl]) = v0;
            *reinterpret_cast<__half2*>(&g_H[(size_t)(r0 + 8) * NH_ + n0 + cl]) = v1;
        }
    }
}

// ---------------------------------------------------------------------------
// GEMM2: out[m, c] = H @ w2[:, c] + sum_g choose[m,g] * b2[g,c]
// ---------------------------------------------------------------------------
__global__ void __launch_bounds__(NT, 3)
gemm2_k(const __half* __restrict__ A, const __half* __restrict__ Bw,
        const float* __restrict__ b2, float* __restrict__ out)
{
    extern __shared__ char smem[];
    int mt, nt;
    tile_map(C_ / BN, mt, nt);
    const int m0 = mt * BM, n0 = nt * BN;

    float acc[4][8][4];
    mainloop(A, NH_, m0, Bw + n0, C_, smem, acc);

    // stage b2 tile [G][BN] in smem
    float* sB2 = (float*)smem;
    const int tid = threadIdx.x;
    for (int i = tid; i < G_ * BN; i += NT)
        sB2[i] = b2[(size_t)(i >> 7) * C_ + n0 + (i & 127)];
    __syncthreads();

    const int lane = tid & 31, warp = tid >> 5;
    const int wm = (warp & 1) * 64, wn = (warp >> 1) * 64;
    const int g8 = lane >> 2, tg = lane & 3;

#pragma unroll
    for (int im = 0; im < 4; im++) {
        const int r0 = m0 + wm + 16 * im + g8;
        float c0[G_], c1[G_];
        *reinterpret_cast<float4*>(&c0[0]) = *reinterpret_cast<const float4*>(&g_choose[r0 * G_]);
        *reinterpret_cast<float4*>(&c0[4]) = *reinterpret_cast<const float4*>(&g_choose[r0 * G_ + 4]);
        *reinterpret_cast<float4*>(&c1[0]) = *reinterpret_cast<const float4*>(&g_choose[(r0 + 8) * G_]);
        *reinterpret_cast<float4*>(&c1[4]) = *reinterpret_cast<const float4*>(&g_choose[(r0 + 8) * G_ + 4]);
#pragma unroll
        for (int in = 0; in < 8; in++) {
            const int cl = wn + 8 * in + 2 * tg;
            float b00 = 0.f, b01 = 0.f, b10 = 0.f, b11 = 0.f;
#pragma unroll
            for (int gg = 0; gg < G_; gg++) {
                const float w0  = sB2[gg * BN + cl];
                const float w1v = sB2[gg * BN + cl + 1];
                b00 += c0[gg] * w0;  b01 += c0[gg] * w1v;
                b10 += c1[gg] * w0;  b11 += c1[gg] * w1v;
            }
            float2 v0, v1;
            v0.x = acc[im][in][0] + b00;  v0.y = acc[im][in][1] + b01;
            v1.x = acc[im][in][2] + b10;  v1.y = acc[im][in][3] + b11;
            *reinterpret_cast<float2*>(&out[(size_t)r0 * C_ + n0 + cl]) = v0;
            *reinterpret_cast<float2*>(&out[(size_t)(r0 + 8) * C_ + n0 + cl]) = v1;
        }
    }
}

// ---------------------------------------------------------------------------
// Pre-pass: fused fp32 -> fp16 conversion of x, w1, w2 (all 33.55M elements)
// ---------------------------------------------------------------------------
#define N8_PER ((size_t)B_ * C_ / 8)   // 4,194,304 uint4-chunks per array

__global__ void __launch_bounds__(256)
f2h_all(const float4* __restrict__ in0, uint4* __restrict__ out0,
        const float4* __restrict__ in1, uint4* __restrict__ out1,
        const float4* __restrict__ in2, uint4* __restrict__ out2)
{
    const size_t total = 3 * N8_PER;
    for (size_t i = (size_t)blockIdx.x * blockDim.x + threadIdx.x; i < total;
         i += (size_t)gridDim.x * blockDim.x) {
        const float4* in;
        uint4* out;
        size_t j;
        if (i < N8_PER)               { in = in0; out = out0; j = i; }
        else if (i < 2 * N8_PER)      { in = in1; out = out1; j = i - N8_PER; }
        else                          { in = in2; out = out2; j = i - 2 * N8_PER; }
        float4 v0 = in[2 * j];
        float4 v1 = in[2 * j + 1];
        uint4 o;
        o.x = h2_bits(__floats2half2_rn(v0.x, v0.y));
        o.y = h2_bits(__floats2half2_rn(v0.z, v0.w));
        o.z = h2_bits(__floats2half2_rn(v1.x, v1.y));
        o.w = h2_bits(__floats2half2_rn(v1.z, v1.w));
        out[j] = o;
    }
}

// ---------------------------------------------------------------------------
// Gate control: choose = softmax(relu(y@wc1+bc1)@wc2+bc2)
// ---------------------------------------------------------------------------
__global__ __launch_bounds__(256)
void gate_kernel(const float* __restrict__ y,
                 const float* __restrict__ wc1, const float* __restrict__ bc1,
                 const float* __restrict__ wc2, const float* __restrict__ bc2)
{
    __shared__ float swc1[CTRL_ * G_];
    __shared__ float swc2[G_ * G_];
    __shared__ float sbc1[G_];
    __shared__ float sbc2[G_];
    const int tid = threadIdx.x;
    for (int i = tid; i < CTRL_ * G_; i += 256) swc1[i] = wc1[i];
    if (tid < G_ * G_) swc2[tid] = wc2[tid];
    if (tid < G_) { sbc1[tid] = bc1[tid]; sbc2[tid] = bc2[tid]; }
    __syncthreads();

    const int b = blockIdx.x * 256 + tid;
    const float* yr = y + (size_t)b * CTRL_;

    float hid[G_];
#pragma unroll
    for (int j = 0; j < G_; j++) hid[j] = sbc1[j];
    for (int c = 0; c < CTRL_; c++) {
        const float yv = yr[c];
#pragma unroll
        for (int j = 0; j < G_; j++) hid[j] += yv * swc1[c * G_ + j];
    }
#pragma unroll
    for (int j = 0; j < G_; j++) hid[j] = fmaxf(hid[j], 0.f);

    float o[G_];
#pragma unroll
    for (int g = 0; g < G_; g++) o[g] = sbc2[g];
#pragma unroll
    for (int j = 0; j < G_; j++)
#pragma unroll
        for (int g = 0; g < G_; g++) o[g] += hid[j] * swc2[j * G_ + g];

    float mx = o[0];
#pragma unroll
    for (int g = 1; g < G_; g++) mx = fmaxf(mx, o[g]);
    float s = 0.f;
#pragma unroll
    for (int g = 0; g < G_; g++) { o[g] = __expf(o[g] - mx); s += o[g]; }
    const float inv = 1.f / s;
#pragma unroll
    for (int g = 0; g < G_; g++) g_choose[b * G_ + g] = o[g] * inv;
}

// ---------------------------------------------------------------------------
extern "C" void kernel_launch(void* const* d_in, const int* in_sizes, int n_in,
                              void* d_out, int out_size)
{
    const float* x   = (const float*)d_in[0];
    const float* y   = (const float*)d_in[1];
    const float* w1  = (const float*)d_in[2];
    const float* b1  = (const float*)d_in[3];
    const float* w2  = (const float*)d_in[4];
    const float* b2  = (const float*)d_in[5];
    const float* wc1 = (const float*)d_in[6];
    const float* bc1 = (const float*)d_in[7];
    const float* wc2 = (const float*)d_in[8];
    const float* bc2 = (const float*)d_in[9];
    float* out = (float*)d_out;

    cudaFuncSetAttribute(gemm1_k, cudaFuncAttributeMaxDynamicSharedMemorySize, SMEM_BYTES);
    cudaFuncSetAttribute(gemm2_k, cudaFuncAttributeMaxDynamicSharedMemorySize, SMEM_BYTES);

    __half* dxh;  cudaGetSymbolAddress((void**)&dxh,  g_xh);
    __half* dw1h; cudaGetSymbolAddress((void**)&dw1h, g_w1h);
    __half* dw2h; cudaGetSymbolAddress((void**)&dw2h, g_w2h);
    __half* dH;   cudaGetSymbolAddress((void**)&dH,   g_H);

    // 8192 blocks: 4x more CTAs in flight for the latency-bound conversion
    f2h_all<<<8192, 256>>>((const float4*)x,  (uint4*)dxh,
                           (const float4*)w1, (uint4*)dw1h,
                           (const float4*)w2, (uint4*)dw2h);
    gate_kernel<<<B_ / 256, 256>>>(y, wc1, bc1, wc2, bc2);
    gemm1_k<<<(B_ / BM) * (NH_ / BN), NT, SMEM_BYTES>>>(dxh, dw1h, b1);
    gemm2_k<<<(B_ / BM) * (C_ / BN), NT, SMEM_BYTES>>>(dH, dw2h, b2, out);
}